// round 1
// baseline (speedup 1.0000x reference)
#include <cuda_runtime.h>

#define BB 4
#define TT 2048
#define CC 1024
#define HH 16
#define DD 64

// Scratch (static device globals: allocation-free per harness rules)
__device__ float g_q[BB*HH*TT*DD];   // [B,H,T,d]
__device__ float g_k[BB*HH*TT*DD];
__device__ float g_v[BB*HH*TT*DD];
__device__ float g_ctx[BB*TT*CC];    // [B,T,C]

// ---------------------------------------------------------------------------
// 128x128x8 register-blocked SGEMM. MODE 0: QKV epilogue scatter into per-head
// Q/K/V scratch. MODE 1: A is g_ctx, plain C write (output projection).
// ---------------------------------------------------------------------------
template<int MODE>
__global__ __launch_bounds__(256)
void sgemm_kernel(const float* __restrict__ Ain, const float* __restrict__ Bw,
                  float* __restrict__ Cout, int M, int N, int K)
{
    __shared__ float As[8][132];   // [k][m], padded (stride 132) for conflict-free transpose stores
    __shared__ float Bs[8][128];   // [k][n]

    const float* __restrict__ A = (MODE == 1) ? (const float*)g_ctx : Ain;

    const int tid = threadIdx.x;
    const int tx  = tid & 15;      // 16 col-groups
    const int ty  = tid >> 4;      // 16 row-groups
    const int m0  = blockIdx.y * 128;
    const int n0  = blockIdx.x * 128;

    const int aRow = tid >> 1;           // 0..127
    const int aCol = (tid & 1) * 4;      // 0 or 4
    const int bRow = tid >> 5;           // 0..7
    const int bCol = (tid & 31) * 4;     // 0..124

    float acc[8][8];
    #pragma unroll
    for (int i = 0; i < 8; i++)
        #pragma unroll
        for (int j = 0; j < 8; j++) acc[i][j] = 0.f;

    for (int k0 = 0; k0 < K; k0 += 8) {
        float4 av = *(const float4*)&A[(m0 + aRow) * K + k0 + aCol];
        float4 bv = *(const float4*)&Bw[(k0 + bRow) * N + n0 + bCol];
        As[aCol + 0][aRow] = av.x;
        As[aCol + 1][aRow] = av.y;
        As[aCol + 2][aRow] = av.z;
        As[aCol + 3][aRow] = av.w;
        *(float4*)&Bs[bRow][bCol] = bv;
        __syncthreads();

        #pragma unroll
        for (int kk = 0; kk < 8; kk++) {
            float a[8], b[8];
            *(float4*)&a[0] = *(const float4*)&As[kk][ty * 4];
            *(float4*)&a[4] = *(const float4*)&As[kk][64 + ty * 4];
            *(float4*)&b[0] = *(const float4*)&Bs[kk][tx * 4];
            *(float4*)&b[4] = *(const float4*)&Bs[kk][64 + tx * 4];
            #pragma unroll
            for (int i = 0; i < 8; i++)
                #pragma unroll
                for (int j = 0; j < 8; j++)
                    acc[i][j] = fmaf(a[i], b[j], acc[i][j]);
        }
        __syncthreads();
    }

    // Epilogue
    #pragma unroll
    for (int i = 0; i < 8; i++) {
        const int r = m0 + ((i < 4) ? (ty * 4 + i) : (64 + ty * 4 + (i - 4)));
        #pragma unroll
        for (int j = 0; j < 8; j++) {
            const int c = n0 + ((j < 4) ? (tx * 4 + j) : (64 + tx * 4 + (j - 4)));
            const float v = acc[i][j];
            if (MODE == 0) {
                // scatter into Q/K/V per-head layout [B,H,T,d]
                const int sel = c >> 10;        // 0:Q 1:K 2:V
                const int cc  = c & 1023;
                const int hh  = cc >> 6;
                const int dd  = cc & 63;
                const int bb  = r >> 11;        // r / 2048
                const int t   = r & 2047;
                const int idx = ((bb * HH + hh) * TT + t) * DD + dd;
                if (sel == 0)      g_q[idx] = v;
                else if (sel == 1) g_k[idx] = v;
                else               g_v[idx] = v;
            } else {
                Cout[r * N + c] = v;
            }
        }
    }
}

// ---------------------------------------------------------------------------
// Flash attention, fp32. Per block: one (b,h), 64 query rows. Loops over 32
// key/value tiles of 64 rows with online softmax. 256 threads, 4x4 microtiles.
// ---------------------------------------------------------------------------
__global__ __launch_bounds__(256)
void flash_kernel()
{
    extern __shared__ float sm[];
    float* Qs = sm;              // [64][68]  transposed: Qs[d][r], pre-scaled by 1/8
    float* Ks = Qs + 64 * 68;    // [64][68]  transposed: Ks[d][c]
    float* Vs = Ks + 64 * 68;    // [64][68]  natural:    Vs[c][d]
    float* Ps = Vs + 64 * 68;    // [64][68]  transposed: Ps[c][r]

    const int bz = blockIdx.z, hh = blockIdx.y, qt = blockIdx.x;
    const int tid = threadIdx.x;
    const int tx = tid & 15;     // d-col / key-col group
    const int ty = tid >> 4;     // query-row group

    const float* __restrict__ Qg = g_q + ((size_t)(bz * HH + hh) * TT + qt * 64) * DD;
    const float* __restrict__ Kg = g_k + (size_t)(bz * HH + hh) * TT * DD;
    const float* __restrict__ Vg = g_v + (size_t)(bz * HH + hh) * TT * DD;

    // Load Q tile transposed, pre-scaled by 1/sqrt(d)=0.125
    #pragma unroll
    for (int rep = 0; rep < 4; rep++) {
        const int lin = tid + rep * 256;
        const int r   = lin >> 4;
        const int d4  = (lin & 15) * 4;
        float4 q = *(const float4*)&Qg[r * DD + d4];
        Qs[(d4 + 0) * 68 + r] = q.x * 0.125f;
        Qs[(d4 + 1) * 68 + r] = q.y * 0.125f;
        Qs[(d4 + 2) * 68 + r] = q.z * 0.125f;
        Qs[(d4 + 3) * 68 + r] = q.w * 0.125f;
    }

    float o[4][4] = {};
    float m_i[4], l_i[4];
    #pragma unroll
    for (int i = 0; i < 4; i++) { m_i[i] = -1e30f; l_i[i] = 0.f; }

    for (int kt = 0; kt < TT / 64; kt++) {
        // Load K (transposed) and V (natural) tiles
        #pragma unroll
        for (int rep = 0; rep < 4; rep++) {
            const int lin = tid + rep * 256;
            const int r   = lin >> 4;
            const int d4  = (lin & 15) * 4;
            float4 kv = *(const float4*)&Kg[(kt * 64 + r) * DD + d4];
            Ks[(d4 + 0) * 68 + r] = kv.x;
            Ks[(d4 + 1) * 68 + r] = kv.y;
            Ks[(d4 + 2) * 68 + r] = kv.z;
            Ks[(d4 + 3) * 68 + r] = kv.w;
            float4 vv = *(const float4*)&Vg[(kt * 64 + r) * DD + d4];
            *(float4*)&Vs[r * 68 + d4] = vv;
        }
        __syncthreads();

        // S = (Q*scale) @ K^T  (64x64, each thread 4x4)
        float s[4][4] = {};
        #pragma unroll 8
        for (int d = 0; d < 64; d++) {
            float4 qv = *(const float4*)&Qs[d * 68 + ty * 4];
            float4 kv = *(const float4*)&Ks[d * 68 + tx * 4];
            const float qa[4] = {qv.x, qv.y, qv.z, qv.w};
            const float kb[4] = {kv.x, kv.y, kv.z, kv.w};
            #pragma unroll
            for (int i = 0; i < 4; i++)
                #pragma unroll
                for (int j = 0; j < 4; j++)
                    s[i][j] = fmaf(qa[i], kb[j], s[i][j]);
        }

        // Online softmax per query row (16 lanes of width-16 group own one row set)
        #pragma unroll
        for (int i = 0; i < 4; i++) {
            float mx = fmaxf(fmaxf(s[i][0], s[i][1]), fmaxf(s[i][2], s[i][3]));
            #pragma unroll
            for (int off = 8; off >= 1; off >>= 1)
                mx = fmaxf(mx, __shfl_xor_sync(0xffffffffu, mx, off, 16));
            const float mnew = fmaxf(m_i[i], mx);
            const float corr = __expf(m_i[i] - mnew);
            float rs = 0.f;
            #pragma unroll
            for (int j = 0; j < 4; j++) {
                s[i][j] = __expf(s[i][j] - mnew);
                rs += s[i][j];
            }
            #pragma unroll
            for (int off = 8; off >= 1; off >>= 1)
                rs += __shfl_xor_sync(0xffffffffu, rs, off, 16);
            l_i[i] = l_i[i] * corr + rs;
            m_i[i] = mnew;
            #pragma unroll
            for (int j = 0; j < 4; j++) o[i][j] *= corr;
        }

        // Stage P transposed for the PV GEMM
        #pragma unroll
        for (int i = 0; i < 4; i++)
            #pragma unroll
            for (int j = 0; j < 4; j++)
                Ps[(tx * 4 + j) * 68 + ty * 4 + i] = s[i][j];
        __syncthreads();

        // O += P @ V
        #pragma unroll 8
        for (int kk = 0; kk < 64; kk++) {
            float4 pv = *(const float4*)&Ps[kk * 68 + ty * 4];
            float4 vv = *(const float4*)&Vs[kk * 68 + tx * 4];
            const float pa[4] = {pv.x, pv.y, pv.z, pv.w};
            const float vb[4] = {vv.x, vv.y, vv.z, vv.w};
            #pragma unroll
            for (int i = 0; i < 4; i++)
                #pragma unroll
                for (int j = 0; j < 4; j++)
                    o[i][j] = fmaf(pa[i], vb[j], o[i][j]);
        }
        __syncthreads();
    }

    // Normalize and write context in [B,T,C] layout (head-merged)
    #pragma unroll
    for (int i = 0; i < 4; i++) {
        const float inv = 1.f / l_i[i];
        const int r = qt * 64 + ty * 4 + i;
        float4 ov = make_float4(o[i][0] * inv, o[i][1] * inv, o[i][2] * inv, o[i][3] * inv);
        *(float4*)&g_ctx[((size_t)bz * TT + r) * CC + hh * 64 + tx * 4] = ov;
    }
}

// ---------------------------------------------------------------------------

extern "C" void kernel_launch(void* const* d_in, const int* in_sizes, int n_in,
                              void* d_out, int out_size)
{
    const float* x    = (const float*)d_in[0];   // [4,2048,1024]
    const float* Wqkv = (const float*)d_in[1];   // [1024,3072]
    const float* Wo   = (const float*)d_in[2];   // [1024,1024]
    float* out = (float*)d_out;                  // [4,2048,1024]

    const int FLASH_SMEM = 4 * 64 * 68 * (int)sizeof(float);  // 69632 B
    cudaFuncSetAttribute(flash_kernel, cudaFuncAttributeMaxDynamicSharedMemorySize,
                         FLASH_SMEM);

    // 1) QKV = x @ W_qkv, scattered into per-head Q/K/V
    sgemm_kernel<0><<<dim3(3 * CC / 128, BB * TT / 128), 256>>>(
        x, Wqkv, nullptr, BB * TT, 3 * CC, CC);

    // 2) flash attention -> g_ctx [B,T,C]
    flash_kernel<<<dim3(TT / 64, HH, BB), 256, FLASH_SMEM>>>();

    // 3) out = ctx @ W_o
    sgemm_kernel<1><<<dim3(CC / 128, BB * TT / 128), 256>>>(
        nullptr, Wo, out, BB * TT, CC, CC);
}

// round 2
// speedup vs baseline: 1.4033x; 1.4033x over previous
#include <cuda_runtime.h>

#define BB 4
#define TT 2048
#define CC 1024
#define HH 16
#define DD 64

// Scratch (static device globals: allocation-free per harness rules)
__device__ float g_q[BB*HH*TT*DD];   // [B,H,T,d]
__device__ float g_k[BB*HH*TT*DD];
__device__ float g_v[BB*HH*TT*DD];
__device__ float g_ctx[BB*TT*CC];    // [B,T,C]

// ---------------------------------------------------------------------------
// tf32 helpers
// ---------------------------------------------------------------------------
__device__ __forceinline__ float tf32r(float x) {
    unsigned u;
    asm("cvt.rna.tf32.f32 %0, %1;" : "=r"(u) : "f"(x));
    return __uint_as_float(u);
}

__device__ __forceinline__ void mma_tf32(float4& d,
                                         unsigned a0, unsigned a1, unsigned a2, unsigned a3,
                                         unsigned b0, unsigned b1,
                                         const float4& c) {
    asm volatile(
        "mma.sync.aligned.m16n8k8.row.col.f32.tf32.tf32.f32 "
        "{%0,%1,%2,%3}, {%4,%5,%6,%7}, {%8,%9}, {%10,%11,%12,%13};\n"
        : "=f"(d.x), "=f"(d.y), "=f"(d.z), "=f"(d.w)
        : "r"(a0), "r"(a1), "r"(a2), "r"(a3),
          "r"(b0), "r"(b1),
          "f"(c.x), "f"(c.y), "f"(c.z), "f"(c.w));
}

// ---------------------------------------------------------------------------
// tf32 tensor-core GEMM: C[M,N] = A[M,K] @ B[K,N], fp32 in/out, tf32 mma.
// Block tile 128x128x32, 256 threads = 8 warps in 2(M) x 4(N), warp tile 64x32.
// MODE 0: QKV epilogue scatter into per-head Q/K/V. MODE 1: plain store (A=g_ctx).
// ---------------------------------------------------------------------------
template<int MODE>
__global__ __launch_bounds__(256)
void gemm_tf32(const float* __restrict__ Ain, const float* __restrict__ Bw,
               float* __restrict__ Cout, int M, int N, int K)
{
    __shared__ float As[32][132];   // [k][m], padded
    __shared__ float Bs[32][132];   // [k][n], padded (132 keeps float4 alignment)

    const float* __restrict__ A = (MODE == 1) ? (const float*)g_ctx : Ain;

    const int tid  = threadIdx.x;
    const int lane = tid & 31;
    const int wid  = tid >> 5;
    const int wm   = wid & 1;       // 2 warps along M
    const int wn   = wid >> 1;      // 4 warps along N
    const int m0   = blockIdx.y * 128;
    const int n0   = blockIdx.x * 128;

    // global load coordinates (per-thread, 4 float4 each for A and B per k-iter)
    const int aRow = tid >> 3;          // 0..31 (stride 32 over 4 passes)
    const int aCol = (tid & 7) * 4;     // 0..28
    const int bRow = tid >> 5;          // 0..7  (stride 8 over 4 passes)
    const int bCol = (tid & 31) * 4;    // 0..124

    float4 aReg[4], bReg[4];

    // prefetch first k-chunk
    #pragma unroll
    for (int p = 0; p < 4; p++) {
        aReg[p] = *(const float4*)&A[(size_t)(m0 + p * 32 + aRow) * K + aCol];
        bReg[p] = *(const float4*)&Bw[(size_t)(p * 8 + bRow) * N + n0 + bCol];
    }

    float4 Cf[4][4];
    #pragma unroll
    for (int i = 0; i < 4; i++)
        #pragma unroll
        for (int j = 0; j < 4; j++) Cf[i][j] = make_float4(0.f, 0.f, 0.f, 0.f);

    const int rb = wm * 64;          // warp M offset in tile
    const int nb = wn * 32;          // warp N offset in tile

    for (int k0 = 0; k0 < K; k0 += 32) {
        // stage prefetched chunk to SMEM (convert to tf32)
        #pragma unroll
        for (int p = 0; p < 4; p++) {
            const int r = p * 32 + aRow;
            As[aCol + 0][r] = tf32r(aReg[p].x);
            As[aCol + 1][r] = tf32r(aReg[p].y);
            As[aCol + 2][r] = tf32r(aReg[p].z);
            As[aCol + 3][r] = tf32r(aReg[p].w);
            float4 bv;
            bv.x = tf32r(bReg[p].x); bv.y = tf32r(bReg[p].y);
            bv.z = tf32r(bReg[p].z); bv.w = tf32r(bReg[p].w);
            *(float4*)&Bs[p * 8 + bRow][bCol] = bv;
        }
        __syncthreads();

        // prefetch next chunk
        if (k0 + 32 < K) {
            #pragma unroll
            for (int p = 0; p < 4; p++) {
                aReg[p] = *(const float4*)&A[(size_t)(m0 + p * 32 + aRow) * K + k0 + 32 + aCol];
                bReg[p] = *(const float4*)&Bw[(size_t)(k0 + 32 + p * 8 + bRow) * N + n0 + bCol];
            }
        }

        // compute: 4 sub-steps of k=8
        #pragma unroll
        for (int kk = 0; kk < 32; kk += 8) {
            unsigned af[4][4], bf[4][2];
            const int kq = kk + (lane & 3);
            const int rq = lane >> 2;
            #pragma unroll
            for (int mt = 0; mt < 4; mt++) {
                const int r0 = rb + mt * 16 + rq;
                af[mt][0] = __float_as_uint(As[kq    ][r0    ]);
                af[mt][1] = __float_as_uint(As[kq    ][r0 + 8]);
                af[mt][2] = __float_as_uint(As[kq + 4][r0    ]);
                af[mt][3] = __float_as_uint(As[kq + 4][r0 + 8]);
            }
            #pragma unroll
            for (int nt = 0; nt < 4; nt++) {
                const int c0 = nb + nt * 8 + rq;
                bf[nt][0] = __float_as_uint(Bs[kq    ][c0]);
                bf[nt][1] = __float_as_uint(Bs[kq + 4][c0]);
            }
            #pragma unroll
            for (int mt = 0; mt < 4; mt++)
                #pragma unroll
                for (int nt = 0; nt < 4; nt++)
                    mma_tf32(Cf[mt][nt],
                             af[mt][0], af[mt][1], af[mt][2], af[mt][3],
                             bf[nt][0], bf[nt][1], Cf[mt][nt]);
        }
        __syncthreads();
    }

    // Epilogue. C fragment (mt,nt): rows r0=lane/4, r0+8; cols c0=2*(lane%4), c0+1.
    #pragma unroll
    for (int mt = 0; mt < 4; mt++) {
        const int r0 = m0 + rb + mt * 16 + (lane >> 2);
        #pragma unroll
        for (int nt = 0; nt < 4; nt++) {
            const int c0 = n0 + nb + nt * 8 + (lane & 3) * 2;
            const float4 v = Cf[mt][nt];
            if (MODE == 1) {
                *(float2*)&Cout[(size_t)r0 * N + c0]       = make_float2(v.x, v.y);
                *(float2*)&Cout[(size_t)(r0 + 8) * N + c0] = make_float2(v.z, v.w);
            } else {
                // scatter into Q/K/V per-head layout [B,H,T,d]
                #pragma unroll
                for (int e = 0; e < 4; e++) {
                    const int r = r0 + ((e >= 2) ? 8 : 0);
                    const int c = c0 + (e & 1);
                    const float val = (e == 0) ? v.x : (e == 1) ? v.y : (e == 2) ? v.z : v.w;
                    const int sel = c >> 10;        // 0:Q 1:K 2:V
                    const int cc  = c & 1023;
                    const int hh  = cc >> 6;
                    const int dd  = cc & 63;
                    const int bb  = r >> 11;
                    const int t   = r & 2047;
                    const int idx = ((bb * HH + hh) * TT + t) * DD + dd;
                    if (sel == 0)      g_q[idx] = val;
                    else if (sel == 1) g_k[idx] = val;
                    else               g_v[idx] = val;
                }
            }
        }
    }
}

// ---------------------------------------------------------------------------
// Flash attention, fp32 (unchanged this round). Per block: one (b,h), 64 query
// rows; 32 key tiles of 64 with online softmax. 256 threads, 4x4 microtiles.
// ---------------------------------------------------------------------------
__global__ __launch_bounds__(256)
void flash_kernel()
{
    extern __shared__ float sm[];
    float* Qs = sm;              // [64][68]  transposed: Qs[d][r], pre-scaled
    float* Ks = Qs + 64 * 68;    // [64][68]  transposed: Ks[d][c]
    float* Vs = Ks + 64 * 68;    // [64][68]  natural:    Vs[c][d]
    float* Ps = Vs + 64 * 68;    // [64][68]  transposed: Ps[c][r]

    const int bz = blockIdx.z, hh = blockIdx.y, qt = blockIdx.x;
    const int tid = threadIdx.x;
    const int tx = tid & 15;
    const int ty = tid >> 4;

    const float* __restrict__ Qg = g_q + ((size_t)(bz * HH + hh) * TT + qt * 64) * DD;
    const float* __restrict__ Kg = g_k + (size_t)(bz * HH + hh) * TT * DD;
    const float* __restrict__ Vg = g_v + (size_t)(bz * HH + hh) * TT * DD;

    #pragma unroll
    for (int rep = 0; rep < 4; rep++) {
        const int lin = tid + rep * 256;
        const int r   = lin >> 4;
        const int d4  = (lin & 15) * 4;
        float4 q = *(const float4*)&Qg[r * DD + d4];
        Qs[(d4 + 0) * 68 + r] = q.x * 0.125f;
        Qs[(d4 + 1) * 68 + r] = q.y * 0.125f;
        Qs[(d4 + 2) * 68 + r] = q.z * 0.125f;
        Qs[(d4 + 3) * 68 + r] = q.w * 0.125f;
    }

    float o[4][4] = {};
    float m_i[4], l_i[4];
    #pragma unroll
    for (int i = 0; i < 4; i++) { m_i[i] = -1e30f; l_i[i] = 0.f; }

    for (int kt = 0; kt < TT / 64; kt++) {
        #pragma unroll
        for (int rep = 0; rep < 4; rep++) {
            const int lin = tid + rep * 256;
            const int r   = lin >> 4;
            const int d4  = (lin & 15) * 4;
            float4 kv = *(const float4*)&Kg[(kt * 64 + r) * DD + d4];
            Ks[(d4 + 0) * 68 + r] = kv.x;
            Ks[(d4 + 1) * 68 + r] = kv.y;
            Ks[(d4 + 2) * 68 + r] = kv.z;
            Ks[(d4 + 3) * 68 + r] = kv.w;
            float4 vv = *(const float4*)&Vg[(kt * 64 + r) * DD + d4];
            *(float4*)&Vs[r * 68 + d4] = vv;
        }
        __syncthreads();

        float s[4][4] = {};
        #pragma unroll 8
        for (int d = 0; d < 64; d++) {
            float4 qv = *(const float4*)&Qs[d * 68 + ty * 4];
            float4 kv = *(const float4*)&Ks[d * 68 + tx * 4];
            const float qa[4] = {qv.x, qv.y, qv.z, qv.w};
            const float kb[4] = {kv.x, kv.y, kv.z, kv.w};
            #pragma unroll
            for (int i = 0; i < 4; i++)
                #pragma unroll
                for (int j = 0; j < 4; j++)
                    s[i][j] = fmaf(qa[i], kb[j], s[i][j]);
        }

        #pragma unroll
        for (int i = 0; i < 4; i++) {
            float mx = fmaxf(fmaxf(s[i][0], s[i][1]), fmaxf(s[i][2], s[i][3]));
            #pragma unroll
            for (int off = 8; off >= 1; off >>= 1)
                mx = fmaxf(mx, __shfl_xor_sync(0xffffffffu, mx, off, 16));
            const float mnew = fmaxf(m_i[i], mx);
            const float corr = __expf(m_i[i] - mnew);
            float rs = 0.f;
            #pragma unroll
            for (int j = 0; j < 4; j++) {
                s[i][j] = __expf(s[i][j] - mnew);
                rs += s[i][j];
            }
            #pragma unroll
            for (int off = 8; off >= 1; off >>= 1)
                rs += __shfl_xor_sync(0xffffffffu, rs, off, 16);
            l_i[i] = l_i[i] * corr + rs;
            m_i[i] = mnew;
            #pragma unroll
            for (int j = 0; j < 4; j++) o[i][j] *= corr;
        }

        #pragma unroll
        for (int i = 0; i < 4; i++)
            #pragma unroll
            for (int j = 0; j < 4; j++)
                Ps[(tx * 4 + j) * 68 + ty * 4 + i] = s[i][j];
        __syncthreads();

        #pragma unroll 8
        for (int kk = 0; kk < 64; kk++) {
            float4 pv = *(const float4*)&Ps[kk * 68 + ty * 4];
            float4 vv = *(const float4*)&Vs[kk * 68 + tx * 4];
            const float pa[4] = {pv.x, pv.y, pv.z, pv.w};
            const float vb[4] = {vv.x, vv.y, vv.z, vv.w};
            #pragma unroll
            for (int i = 0; i < 4; i++)
                #pragma unroll
                for (int j = 0; j < 4; j++)
                    o[i][j] = fmaf(pa[i], vb[j], o[i][j]);
        }
        __syncthreads();
    }

    #pragma unroll
    for (int i = 0; i < 4; i++) {
        const float inv = 1.f / l_i[i];
        const int r = qt * 64 + ty * 4 + i;
        float4 ov = make_float4(o[i][0] * inv, o[i][1] * inv, o[i][2] * inv, o[i][3] * inv);
        *(float4*)&g_ctx[((size_t)bz * TT + r) * CC + hh * 64 + tx * 4] = ov;
    }
}

// ---------------------------------------------------------------------------

extern "C" void kernel_launch(void* const* d_in, const int* in_sizes, int n_in,
                              void* d_out, int out_size)
{
    const float* x    = (const float*)d_in[0];   // [4,2048,1024]
    const float* Wqkv = (const float*)d_in[1];   // [1024,3072]
    const float* Wo   = (const float*)d_in[2];   // [1024,1024]
    float* out = (float*)d_out;                  // [4,2048,1024]

    const int FLASH_SMEM = 4 * 64 * 68 * (int)sizeof(float);  // 69632 B
    cudaFuncSetAttribute(flash_kernel, cudaFuncAttributeMaxDynamicSharedMemorySize,
                         FLASH_SMEM);

    // 1) QKV = x @ W_qkv (tf32 tensor cores), scattered into per-head Q/K/V
    gemm_tf32<0><<<dim3(3 * CC / 128, BB * TT / 128), 256>>>(
        x, Wqkv, nullptr, BB * TT, 3 * CC, CC);

    // 2) flash attention -> g_ctx [B,T,C]
    flash_kernel<<<dim3(TT / 64, HH, BB), 256, FLASH_SMEM>>>();

    // 3) out = ctx @ W_o (tf32 tensor cores)
    gemm_tf32<1><<<dim3(CC / 128, BB * TT / 128), 256>>>(
        nullptr, Wo, out, BB * TT, CC, CC);
}

// round 3
// speedup vs baseline: 2.9757x; 2.1204x over previous
#include <cuda_runtime.h>

#define BB 4
#define TT 2048
#define CC 1024
#define HH 16
#define DD 64

// Scratch (static device globals: allocation-free per harness rules)
__device__ float g_q[BB*HH*TT*DD];   // [B,H,T,d]
__device__ float g_k[BB*HH*TT*DD];
__device__ float g_v[BB*HH*TT*DD];
__device__ float g_ctx[BB*TT*CC];    // [B,T,C]

// ---------------------------------------------------------------------------
// helpers
// ---------------------------------------------------------------------------
__device__ __forceinline__ float tf32r(float x) {
    unsigned u;
    asm("cvt.rna.tf32.f32 %0, %1;" : "=r"(u) : "f"(x));
    return __uint_as_float(u);
}

__device__ __forceinline__ void mma_tf32(float4& d,
                                         unsigned a0, unsigned a1, unsigned a2, unsigned a3,
                                         unsigned b0, unsigned b1,
                                         const float4& c) {
    asm volatile(
        "mma.sync.aligned.m16n8k8.row.col.f32.tf32.tf32.f32 "
        "{%0,%1,%2,%3}, {%4,%5,%6,%7}, {%8,%9}, {%10,%11,%12,%13};\n"
        : "=f"(d.x), "=f"(d.y), "=f"(d.z), "=f"(d.w)
        : "r"(a0), "r"(a1), "r"(a2), "r"(a3),
          "r"(b0), "r"(b1),
          "f"(c.x), "f"(c.y), "f"(c.z), "f"(c.w));
}

__device__ __forceinline__ void ldsm4(unsigned& r0, unsigned& r1, unsigned& r2, unsigned& r3,
                                      unsigned saddr) {
    asm volatile("ldmatrix.sync.aligned.m8n8.x4.shared.b16 {%0,%1,%2,%3}, [%4];"
                 : "=r"(r0), "=r"(r1), "=r"(r2), "=r"(r3) : "r"(saddr));
}

// Branch-free exp2 using only FMA/ALU pipes (no MUFU). Valid for y <= ~0,
// clamps at -126 (returns ~0 for very negative args). Rel err ~2e-6.
__device__ __forceinline__ float fexp2(float y) {
    y = fmaxf(y, -126.0f);
    float t = y + 12582912.0f;                       // round-to-nearest in low mantissa
    int   n = __float_as_int(t) << 23;               // (round(y)) << 23  (wraps clean)
    float f = y - (t - 12582912.0f);                 // f in [-0.5, 0.5]
    float p =            1.3333558e-3f;
    p = fmaf(p, f, 9.6181291e-3f);
    p = fmaf(p, f, 5.5504109e-2f);
    p = fmaf(p, f, 2.4022651e-1f);
    p = fmaf(p, f, 6.9314718e-1f);
    p = fmaf(p, f, 1.0f);
    return __int_as_float(__float_as_int(p) + n);
}

// ---------------------------------------------------------------------------
// tf32 tensor-core GEMM (unchanged from round 2).
// Block tile 128x128x32, 256 threads = 8 warps in 2(M) x 4(N), warp tile 64x32.
// MODE 0: QKV epilogue scatter into per-head Q/K/V. MODE 1: plain store (A=g_ctx).
// ---------------------------------------------------------------------------
template<int MODE>
__global__ __launch_bounds__(256)
void gemm_tf32(const float* __restrict__ Ain, const float* __restrict__ Bw,
               float* __restrict__ Cout, int M, int N, int K)
{
    __shared__ float As[32][132];
    __shared__ float Bs[32][132];

    const float* __restrict__ A = (MODE == 1) ? (const float*)g_ctx : Ain;

    const int tid  = threadIdx.x;
    const int lane = tid & 31;
    const int wid  = tid >> 5;
    const int wm   = wid & 1;
    const int wn   = wid >> 1;
    const int m0   = blockIdx.y * 128;
    const int n0   = blockIdx.x * 128;

    const int aRow = tid >> 3;
    const int aCol = (tid & 7) * 4;
    const int bRow = tid >> 5;
    const int bCol = (tid & 31) * 4;

    float4 aReg[4], bReg[4];
    #pragma unroll
    for (int p = 0; p < 4; p++) {
        aReg[p] = *(const float4*)&A[(size_t)(m0 + p * 32 + aRow) * K + aCol];
        bReg[p] = *(const float4*)&Bw[(size_t)(p * 8 + bRow) * N + n0 + bCol];
    }

    float4 Cf[4][4];
    #pragma unroll
    for (int i = 0; i < 4; i++)
        #pragma unroll
        for (int j = 0; j < 4; j++) Cf[i][j] = make_float4(0.f, 0.f, 0.f, 0.f);

    const int rb = wm * 64;
    const int nb = wn * 32;

    for (int k0 = 0; k0 < K; k0 += 32) {
        #pragma unroll
        for (int p = 0; p < 4; p++) {
            const int r = p * 32 + aRow;
            As[aCol + 0][r] = tf32r(aReg[p].x);
            As[aCol + 1][r] = tf32r(aReg[p].y);
            As[aCol + 2][r] = tf32r(aReg[p].z);
            As[aCol + 3][r] = tf32r(aReg[p].w);
            float4 bv;
            bv.x = tf32r(bReg[p].x); bv.y = tf32r(bReg[p].y);
            bv.z = tf32r(bReg[p].z); bv.w = tf32r(bReg[p].w);
            *(float4*)&Bs[p * 8 + bRow][bCol] = bv;
        }
        __syncthreads();

        if (k0 + 32 < K) {
            #pragma unroll
            for (int p = 0; p < 4; p++) {
                aReg[p] = *(const float4*)&A[(size_t)(m0 + p * 32 + aRow) * K + k0 + 32 + aCol];
                bReg[p] = *(const float4*)&Bw[(size_t)(k0 + 32 + p * 8 + bRow) * N + n0 + bCol];
            }
        }

        #pragma unroll
        for (int kk = 0; kk < 32; kk += 8) {
            unsigned af[4][4], bf[4][2];
            const int kq = kk + (lane & 3);
            const int rq = lane >> 2;
            #pragma unroll
            for (int mt = 0; mt < 4; mt++) {
                const int r0 = rb + mt * 16 + rq;
                af[mt][0] = __float_as_uint(As[kq    ][r0    ]);
                af[mt][1] = __float_as_uint(As[kq    ][r0 + 8]);
                af[mt][2] = __float_as_uint(As[kq + 4][r0    ]);
                af[mt][3] = __float_as_uint(As[kq + 4][r0 + 8]);
            }
            #pragma unroll
            for (int nt = 0; nt < 4; nt++) {
                const int c0 = nb + nt * 8 + rq;
                bf[nt][0] = __float_as_uint(Bs[kq    ][c0]);
                bf[nt][1] = __float_as_uint(Bs[kq + 4][c0]);
            }
            #pragma unroll
            for (int mt = 0; mt < 4; mt++)
                #pragma unroll
                for (int nt = 0; nt < 4; nt++)
                    mma_tf32(Cf[mt][nt],
                             af[mt][0], af[mt][1], af[mt][2], af[mt][3],
                             bf[nt][0], bf[nt][1], Cf[mt][nt]);
        }
        __syncthreads();
    }

    #pragma unroll
    for (int mt = 0; mt < 4; mt++) {
        const int r0 = m0 + rb + mt * 16 + (lane >> 2);
        #pragma unroll
        for (int nt = 0; nt < 4; nt++) {
            const int c0 = n0 + nb + nt * 8 + (lane & 3) * 2;
            const float4 v = Cf[mt][nt];
            if (MODE == 1) {
                *(float2*)&Cout[(size_t)r0 * N + c0]       = make_float2(v.x, v.y);
                *(float2*)&Cout[(size_t)(r0 + 8) * N + c0] = make_float2(v.z, v.w);
            } else {
                #pragma unroll
                for (int e = 0; e < 4; e++) {
                    const int r = r0 + ((e >= 2) ? 8 : 0);
                    const int c = c0 + (e & 1);
                    const float val = (e == 0) ? v.x : (e == 1) ? v.y : (e == 2) ? v.z : v.w;
                    const int sel = c >> 10;
                    const int cc  = c & 1023;
                    const int hh  = cc >> 6;
                    const int dd  = cc & 63;
                    const int bb  = r >> 11;
                    const int t   = r & 2047;
                    const int idx = ((bb * HH + hh) * TT + t) * DD + dd;
                    if (sel == 0)      g_q[idx] = val;
                    else if (sel == 1) g_k[idx] = val;
                    else               g_v[idx] = val;
                }
            }
        }
    }
}

// ---------------------------------------------------------------------------
// Tensor-core flash attention (tf32 mma, log2-domain softmax, FMA-only exp2).
// Block: 128 threads = 4 warps; q-tile 128 rows (warp = m32 x n64), 32 k-tiles
// of 64 keys. Smem: Qs[128][68] + Ks[64][68] + Vt[64][68] = 68KB -> 2 blocks/SM.
// ---------------------------------------------------------------------------
__global__ __launch_bounds__(128)
void flash_mma()
{
    extern __shared__ float sm[];
    float* Qs = sm;                  // [128][68]  Qs[q][d], scaled by 0.125*log2e, tf32
    float* Ks = sm + 128 * 68;       // [64][68]   Ks[key][d], tf32
    float* Vt = sm + 192 * 68;       // [64][68]   Vt[d][key], tf32

    const int bz = blockIdx.z, hh = blockIdx.y;
    const int qbase = blockIdx.x * 128;
    const int tid  = threadIdx.x;
    const int lane = tid & 31;
    const int w    = tid >> 5;
    const unsigned sbase = (unsigned)__cvta_generic_to_shared(sm);

    const float* __restrict__ Qg = g_q + ((size_t)(bz * HH + hh) * TT + qbase) * DD;
    const float* __restrict__ Kg = g_k + (size_t)(bz * HH + hh) * TT * DD;
    const float* __restrict__ Vg = g_v + (size_t)(bz * HH + hh) * TT * DD;

    // stage Q once (scale folds softmax 1/sqrt(d) and log2e)
    const float qscale = 0.125f * 1.4426950408889634f;
    #pragma unroll
    for (int rep = 0; rep < 16; rep++) {
        const int row = (tid >> 4) + rep * 8;
        const int col = (tid & 15) * 4;
        float4 v = *(const float4*)&Qg[row * DD + col];
        float4 o;
        o.x = tf32r(v.x * qscale); o.y = tf32r(v.y * qscale);
        o.z = tf32r(v.z * qscale); o.w = tf32r(v.w * qscale);
        *(float4*)&Qs[row * 68 + col] = o;
    }

    float4 of[2][8];
    #pragma unroll
    for (int mt = 0; mt < 2; mt++)
        #pragma unroll
        for (int nf = 0; nf < 8; nf++) of[mt][nf] = make_float4(0.f, 0.f, 0.f, 0.f);
    float mrow[2][2], lrow[2][2];
    #pragma unroll
    for (int mt = 0; mt < 2; mt++) {
        mrow[mt][0] = mrow[mt][1] = -1e30f;
        lrow[mt][0] = lrow[mt][1] = 0.f;
    }

    // ldmatrix per-lane address geometry
    const int grp = lane >> 3, lr = lane & 7;
    const int a_r = lr + ((grp & 1) << 3);   // A: M0 rows,k0 | M1 rows+8,k0 | M2 rows,k+4 | M3 rows+8,k+4
    const int a_k = (grp >> 1) << 2;
    const int b_n = lr + ((grp >> 1) << 3);  // B: M0 n,k0 | M1 n,k+4 | M2 n+8,k0 | M3 n+8,k+4
    const int b_k = (grp & 1) << 2;
    const int qsel = lane & 3;               // quad index for P shuffle
    const int qb   = lane & ~3;

    for (int kt = 0; kt < 32; kt++) {
        __syncthreads();
        // stage K (natural [key][d])
        #pragma unroll
        for (int rep = 0; rep < 8; rep++) {
            const int row = (tid >> 4) + rep * 8;
            const int col = (tid & 15) * 4;
            float4 v = *(const float4*)&Kg[(size_t)(kt * 64 + row) * DD + col];
            float4 o;
            o.x = tf32r(v.x); o.y = tf32r(v.y); o.z = tf32r(v.z); o.w = tf32r(v.w);
            *(float4*)&Ks[row * 68 + col] = o;
        }
        // stage V transposed (Vt[d][key]); per-thread: one d, 8 key-quads
        {
            const int d  = tid & 63;
            const int qp = tid >> 6;
            #pragma unroll
            for (int rep = 0; rep < 8; rep++) {
                const int k4 = (qp + rep * 2) * 4;
                float4 o;
                o.x = tf32r(Vg[(size_t)(kt * 64 + k4 + 0) * DD + d]);
                o.y = tf32r(Vg[(size_t)(kt * 64 + k4 + 1) * DD + d]);
                o.z = tf32r(Vg[(size_t)(kt * 64 + k4 + 2) * DD + d]);
                o.w = tf32r(Vg[(size_t)(kt * 64 + k4 + 3) * DD + d]);
                *(float4*)&Vt[d * 68 + k4] = o;
            }
        }
        __syncthreads();

        // ---- S = Q @ K^T (per warp: m32 x n64, k=64) ----
        float4 sf[2][8];
        #pragma unroll
        for (int mt = 0; mt < 2; mt++)
            #pragma unroll
            for (int nf = 0; nf < 8; nf++) sf[mt][nf] = make_float4(0.f, 0.f, 0.f, 0.f);

        #pragma unroll
        for (int ks = 0; ks < 8; ks++) {
            unsigned qa[2][4];
            #pragma unroll
            for (int mt = 0; mt < 2; mt++)
                ldsm4(qa[mt][0], qa[mt][1], qa[mt][2], qa[mt][3],
                      sbase + (unsigned)(((w * 32 + mt * 16 + a_r) * 68 + ks * 8 + a_k) << 2));
            unsigned kb[8][2];
            #pragma unroll
            for (int nfp = 0; nfp < 4; nfp++) {
                unsigned r0, r1, r2, r3;
                ldsm4(r0, r1, r2, r3,
                      sbase + (unsigned)((128 * 68 + (nfp * 16 + b_n) * 68 + ks * 8 + b_k) << 2));
                kb[2 * nfp][0] = r0; kb[2 * nfp][1] = r1;
                kb[2 * nfp + 1][0] = r2; kb[2 * nfp + 1][1] = r3;
            }
            #pragma unroll
            for (int mt = 0; mt < 2; mt++)
                #pragma unroll
                for (int nf = 0; nf < 8; nf++)
                    mma_tf32(sf[mt][nf], qa[mt][0], qa[mt][1], qa[mt][2], qa[mt][3],
                             kb[nf][0], kb[nf][1], sf[mt][nf]);
        }

        // ---- online softmax (log2 domain, FMA-only exp2) ----
        #pragma unroll
        for (int mt = 0; mt < 2; mt++) {
            float mx0 = -1e30f, mx1 = -1e30f;
            #pragma unroll
            for (int nf = 0; nf < 8; nf++) {
                mx0 = fmaxf(mx0, fmaxf(sf[mt][nf].x, sf[mt][nf].y));
                mx1 = fmaxf(mx1, fmaxf(sf[mt][nf].z, sf[mt][nf].w));
            }
            mx0 = fmaxf(mx0, __shfl_xor_sync(0xffffffffu, mx0, 1));
            mx0 = fmaxf(mx0, __shfl_xor_sync(0xffffffffu, mx0, 2));
            mx1 = fmaxf(mx1, __shfl_xor_sync(0xffffffffu, mx1, 1));
            mx1 = fmaxf(mx1, __shfl_xor_sync(0xffffffffu, mx1, 2));
            const float mn0 = fmaxf(mrow[mt][0], mx0);
            const float mn1 = fmaxf(mrow[mt][1], mx1);
            const float corr0 = fexp2(mrow[mt][0] - mn0);
            const float corr1 = fexp2(mrow[mt][1] - mn1);
            mrow[mt][0] = mn0; mrow[mt][1] = mn1;

            float rs0 = 0.f, rs1 = 0.f;
            #pragma unroll
            for (int nf = 0; nf < 8; nf++) {
                float4& s = sf[mt][nf];
                s.x = tf32r(fexp2(s.x - mn0));
                s.y = tf32r(fexp2(s.y - mn0));
                s.z = tf32r(fexp2(s.z - mn1));
                s.w = tf32r(fexp2(s.w - mn1));
                rs0 += s.x + s.y;
                rs1 += s.z + s.w;
            }
            rs0 += __shfl_xor_sync(0xffffffffu, rs0, 1);
            rs0 += __shfl_xor_sync(0xffffffffu, rs0, 2);
            rs1 += __shfl_xor_sync(0xffffffffu, rs1, 1);
            rs1 += __shfl_xor_sync(0xffffffffu, rs1, 2);
            lrow[mt][0] = lrow[mt][0] * corr0 + rs0;
            lrow[mt][1] = lrow[mt][1] * corr1 + rs1;
            #pragma unroll
            for (int nf = 0; nf < 8; nf++) {
                of[mt][nf].x *= corr0; of[mt][nf].y *= corr0;
                of[mt][nf].z *= corr1; of[mt][nf].w *= corr1;
            }
        }

        // ---- O += P @ V  (P via quad shuffles C-frag -> A-frag; V via ldmatrix) ----
        #pragma unroll
        for (int ks = 0; ks < 8; ks++) {
            unsigned vb[8][2];
            #pragma unroll
            for (int nfp = 0; nfp < 4; nfp++) {
                unsigned r0, r1, r2, r3;
                ldsm4(r0, r1, r2, r3,
                      sbase + (unsigned)((192 * 68 + (nfp * 16 + b_n) * 68 + ks * 8 + b_k) << 2));
                vb[2 * nfp][0] = r0; vb[2 * nfp][1] = r1;
                vb[2 * nfp + 1][0] = r2; vb[2 * nfp + 1][1] = r3;
            }
            #pragma unroll
            for (int mt = 0; mt < 2; mt++) {
                const float4 s = sf[mt][ks];
                const int s0 = qb + (qsel >> 1);
                const int s1 = s0 + 2;
                const float x0 = __shfl_sync(0xffffffffu, s.x, s0);
                const float y0 = __shfl_sync(0xffffffffu, s.y, s0);
                const float z0 = __shfl_sync(0xffffffffu, s.z, s0);
                const float w0 = __shfl_sync(0xffffffffu, s.w, s0);
                const float x1 = __shfl_sync(0xffffffffu, s.x, s1);
                const float y1 = __shfl_sync(0xffffffffu, s.y, s1);
                const float z1 = __shfl_sync(0xffffffffu, s.z, s1);
                const float w1 = __shfl_sync(0xffffffffu, s.w, s1);
                const bool odd = qsel & 1;
                const unsigned a0 = __float_as_uint(odd ? y0 : x0);
                const unsigned a1 = __float_as_uint(odd ? w0 : z0);
                const unsigned a2 = __float_as_uint(odd ? y1 : x1);
                const unsigned a3 = __float_as_uint(odd ? w1 : z1);
                #pragma unroll
                for (int nf = 0; nf < 8; nf++)
                    mma_tf32(of[mt][nf], a0, a1, a2, a3, vb[nf][0], vb[nf][1], of[mt][nf]);
            }
        }
    }

    // ---- epilogue: normalize, write context [B,T,C] ----
    #pragma unroll
    for (int mt = 0; mt < 2; mt++) {
        const float inv0 = 1.f / lrow[mt][0];
        const float inv1 = 1.f / lrow[mt][1];
        const int r0 = qbase + w * 32 + mt * 16 + (lane >> 2);
        #pragma unroll
        for (int nf = 0; nf < 8; nf++) {
            const int c = hh * 64 + nf * 8 + (lane & 3) * 2;
            *(float2*)&g_ctx[((size_t)bz * TT + r0) * CC + c] =
                make_float2(of[mt][nf].x * inv0, of[mt][nf].y * inv0);
            *(float2*)&g_ctx[((size_t)bz * TT + r0 + 8) * CC + c] =
                make_float2(of[mt][nf].z * inv1, of[mt][nf].w * inv1);
        }
    }
}

// ---------------------------------------------------------------------------

extern "C" void kernel_launch(void* const* d_in, const int* in_sizes, int n_in,
                              void* d_out, int out_size)
{
    const float* x    = (const float*)d_in[0];   // [4,2048,1024]
    const float* Wqkv = (const float*)d_in[1];   // [1024,3072]
    const float* Wo   = (const float*)d_in[2];   // [1024,1024]
    float* out = (float*)d_out;                  // [4,2048,1024]

    const int FLASH_SMEM = 256 * 68 * (int)sizeof(float);  // 69632 B
    cudaFuncSetAttribute(flash_mma, cudaFuncAttributeMaxDynamicSharedMemorySize,
                         FLASH_SMEM);

    // 1) QKV = x @ W_qkv (tf32 tensor cores), scattered into per-head Q/K/V
    gemm_tf32<0><<<dim3(3 * CC / 128, BB * TT / 128), 256>>>(
        x, Wqkv, nullptr, BB * TT, 3 * CC, CC);

    // 2) tensor-core flash attention -> g_ctx [B,T,C]
    flash_mma<<<dim3(TT / 128, HH, BB), 128, FLASH_SMEM>>>();

    // 3) out = ctx @ W_o (tf32 tensor cores)
    gemm_tf32<1><<<dim3(CC / 128, BB * TT / 128), 256>>>(
        nullptr, Wo, out, BB * TT, CC, CC);
}

// round 5
// speedup vs baseline: 3.6874x; 1.2392x over previous
#include <cuda_runtime.h>
#include <cstdint>

#define BB 4
#define TT 2048
#define CC 1024
#define HH 16
#define DD 64

// Scratch (static device globals: allocation-free per harness rules)
__device__ float g_q[BB*HH*TT*DD];   // [B,H,T,d]
__device__ float g_k[BB*HH*TT*DD];
__device__ float g_v[BB*HH*TT*DD];
__device__ float g_ctx[BB*TT*CC];    // [B,T,C]
__device__ float g_wqkvt[3*CC*CC];   // W_qkv^T [3C, C], tf32-rounded
__device__ float g_wot[CC*CC];       // W_o^T   [C, C],  tf32-rounded

// ---------------------------------------------------------------------------
// helpers
// ---------------------------------------------------------------------------
__device__ __forceinline__ float tf32r(float x) {
    unsigned u;
    asm("cvt.rna.tf32.f32 %0, %1;" : "=r"(u) : "f"(x));
    return __uint_as_float(u);
}
__device__ __forceinline__ unsigned tf32u(unsigned x) {
    unsigned u;
    asm("cvt.rna.tf32.f32 %0, %1;" : "=r"(u) : "f"(__uint_as_float(x)));
    return u;
}

__device__ __forceinline__ void mma_tf32(float4& d,
                                         unsigned a0, unsigned a1, unsigned a2, unsigned a3,
                                         unsigned b0, unsigned b1,
                                         const float4& c) {
    asm volatile(
        "mma.sync.aligned.m16n8k8.row.col.f32.tf32.tf32.f32 "
        "{%0,%1,%2,%3}, {%4,%5,%6,%7}, {%8,%9}, {%10,%11,%12,%13};\n"
        : "=f"(d.x), "=f"(d.y), "=f"(d.z), "=f"(d.w)
        : "r"(a0), "r"(a1), "r"(a2), "r"(a3),
          "r"(b0), "r"(b1),
          "f"(c.x), "f"(c.y), "f"(c.z), "f"(c.w));
}

__device__ __forceinline__ void ldsm4(unsigned& r0, unsigned& r1, unsigned& r2, unsigned& r3,
                                      unsigned saddr) {
    asm volatile("ldmatrix.sync.aligned.m8n8.x4.shared.b16 {%0,%1,%2,%3}, [%4];"
                 : "=r"(r0), "=r"(r1), "=r"(r2), "=r"(r3) : "r"(saddr));
}

#define CP_ASYNC16(saddr, gptr) \
    asm volatile("cp.async.cg.shared.global [%0], [%1], 16;" \
                 :: "r"((uint32_t)(saddr)), "l"(gptr))
#define CP_COMMIT() asm volatile("cp.async.commit_group;" ::: "memory")
#define CP_WAIT0()  asm volatile("cp.async.wait_group 0;" ::: "memory")
#define CP_WAIT1()  asm volatile("cp.async.wait_group 1;" ::: "memory")

// Branch-free exp2 using only FMA/ALU pipes (no MUFU).
__device__ __forceinline__ float fexp2(float y) {
    y = fmaxf(y, -126.0f);
    float t = y + 12582912.0f;
    int   n = __float_as_int(t) << 23;
    float f = y - (t - 12582912.0f);
    float p =            1.3333558e-3f;
    p = fmaf(p, f, 9.6181291e-3f);
    p = fmaf(p, f, 5.5504109e-2f);
    p = fmaf(p, f, 2.4022651e-1f);
    p = fmaf(p, f, 6.9314718e-1f);
    p = fmaf(p, f, 1.0f);
    return __int_as_float(__float_as_int(p) + n);
}

// ---------------------------------------------------------------------------
// Weight transpose + tf32 rounding: Wt[n][k] = tf32(W[k][n]).  W is [K, N].
// ---------------------------------------------------------------------------
__global__ __launch_bounds__(256)
void transpose_round(const float* __restrict__ W, float* __restrict__ Wt, int K, int N)
{
    __shared__ float t[32][33];
    const int n0 = blockIdx.x * 32, k0 = blockIdx.y * 32;
    const int tx = threadIdx.x, ty = threadIdx.y;   // 32 x 8
    #pragma unroll
    for (int i = 0; i < 32; i += 8)
        t[ty + i][tx] = W[(size_t)(k0 + ty + i) * N + n0 + tx];
    __syncthreads();
    #pragma unroll
    for (int i = 0; i < 32; i += 8)
        Wt[(size_t)(n0 + ty + i) * K + k0 + tx] = tf32r(t[tx][ty + i]);
}

// ---------------------------------------------------------------------------
// mma.sync tf32 GEMM, L1-optimized.
// C[128,128] per CTA = A[128,K] @ Bt[128,K]^T, both K-major.
// 128 threads = 4 warps in 2(M) x 2(N); warp tile 64x64.
// SMEM K-major tiles, row stride 36 floats (conflict-free ldmatrix),
// cp.async double buffering; A fragments tf32-rounded in registers.
// MODE 0: QKV scatter epilogue. MODE 1: plain store (A = g_ctx).
// ---------------------------------------------------------------------------
static constexpr int TSTRIDE  = 36;                        // floats per smem row
static constexpr int TILEB    = 128 * TSTRIDE * 4;         // 18432 B per operand tile
static constexpr int BUF      = 2 * TILEB;                 // A+B per stage buffer
static constexpr int GEMM_SMEM = 2 * BUF;                  // 73728 B

template<int MODE>
__global__ __launch_bounds__(128, 2)
void gemm_mma(const float* __restrict__ Ain, const float* __restrict__ Bt,
              float* __restrict__ Cout, int Ksz, int Nsz)
{
    extern __shared__ float smem[];
    const uint32_t sb = (uint32_t)__cvta_generic_to_shared(smem);
    const int tid = threadIdx.x, lane = tid & 31, wid = tid >> 5;
    const int wm = wid & 1, wn = wid >> 1;
    const int m0 = blockIdx.y * 128, n0 = blockIdx.x * 128;
    const float* __restrict__ A = (MODE == 1) ? (const float*)g_ctx : Ain;

    const float* __restrict__ Ag = A  + (size_t)m0 * Ksz;
    const float* __restrict__ Bg = Bt + (size_t)n0 * Ksz;

    // per-thread staging coords: 8 x 16B for A, 8 x 16B for B per chunk
    const int srow = tid >> 3;           // 0..15 (stride 16 over 8 passes? no: idx below)
    (void)srow;

    auto stage = [&](int buf, int jj) {
        const uint32_t sA = sb + buf * BUF;
        const uint32_t sB = sA + TILEB;
        const float* ga = Ag + jj * 32;
        const float* gb = Bg + jj * 32;
        #pragma unroll
        for (int it = 0; it < 8; it++) {
            const int idx = tid + it * 128;      // 0..1023
            const int row = idx >> 3;
            const int c4  = (idx & 7) << 2;
            CP_ASYNC16(sA + ((row * TSTRIDE + c4) << 2), ga + (size_t)row * Ksz + c4);
            CP_ASYNC16(sB + ((row * TSTRIDE + c4) << 2), gb + (size_t)row * Ksz + c4);
        }
    };

    const int NCH = Ksz / 32;

    stage(0, 0); CP_COMMIT();
    stage(1, 1); CP_COMMIT();

    float4 Cf[4][8];
    #pragma unroll
    for (int i = 0; i < 4; i++)
        #pragma unroll
        for (int j = 0; j < 8; j++) Cf[i][j] = make_float4(0.f, 0.f, 0.f, 0.f);

    // ldmatrix per-lane geometry (validated in flash kernel)
    const int grp = lane >> 3, lr = lane & 7;
    const int a_r = lr + ((grp & 1) << 3);
    const int a_k = (grp >> 1) << 2;
    const int b_n = lr + ((grp >> 1) << 3);
    const int b_k = (grp & 1) << 2;

    for (int j = 0; j < NCH; j++) {
        if (j + 1 < NCH) { CP_WAIT1(); } else { CP_WAIT0(); }
        __syncthreads();

        const uint32_t sA = sb + (j & 1) * BUF;
        const uint32_t sB = sA + TILEB;

        #pragma unroll
        for (int ks = 0; ks < 4; ks++) {
            unsigned af[4][4];
            #pragma unroll
            for (int mt = 0; mt < 4; mt++) {
                ldsm4(af[mt][0], af[mt][1], af[mt][2], af[mt][3],
                      sA + (((wm * 64 + mt * 16 + a_r) * TSTRIDE + ks * 8 + a_k) << 2));
                af[mt][0] = tf32u(af[mt][0]); af[mt][1] = tf32u(af[mt][1]);
                af[mt][2] = tf32u(af[mt][2]); af[mt][3] = tf32u(af[mt][3]);
            }
            unsigned bf[8][2];
            #pragma unroll
            for (int nfp = 0; nfp < 4; nfp++) {
                unsigned r0, r1, r2, r3;
                ldsm4(r0, r1, r2, r3,
                      sB + (((wn * 64 + nfp * 16 + b_n) * TSTRIDE + ks * 8 + b_k) << 2));
                bf[2 * nfp][0] = r0; bf[2 * nfp][1] = r1;
                bf[2 * nfp + 1][0] = r2; bf[2 * nfp + 1][1] = r3;
            }
            #pragma unroll
            for (int mt = 0; mt < 4; mt++)
                #pragma unroll
                for (int nf = 0; nf < 8; nf++)
                    mma_tf32(Cf[mt][nf], af[mt][0], af[mt][1], af[mt][2], af[mt][3],
                             bf[nf][0], bf[nf][1], Cf[mt][nf]);
        }
        __syncthreads();
        if (j + 2 < NCH) { stage(j & 1, j + 2); CP_COMMIT(); }
    }

    // epilogue
    #pragma unroll
    for (int mt = 0; mt < 4; mt++) {
        const int r0 = m0 + wm * 64 + mt * 16 + (lane >> 2);
        #pragma unroll
        for (int nf = 0; nf < 8; nf++) {
            const int c0 = n0 + wn * 64 + nf * 8 + (lane & 3) * 2;
            const float4 v = Cf[mt][nf];
            if (MODE == 1) {
                *(float2*)&Cout[(size_t)r0 * Nsz + c0]       = make_float2(v.x, v.y);
                *(float2*)&Cout[(size_t)(r0 + 8) * Nsz + c0] = make_float2(v.z, v.w);
            } else {
                const int sel = c0 >> 10;        // 0:Q 1:K 2:V (pair never crosses)
                const int cc  = c0 & 1023;
                const int hh2 = cc >> 6;
                const int ddb = cc & 63;
                float* base = (sel == 0) ? g_q : (sel == 1) ? g_k : g_v;
                const int bb2a = r0 >> 11, t2a = r0 & 2047;
                const int bb2b = (r0 + 8) >> 11, t2b = (r0 + 8) & 2047;
                *(float2*)&base[((size_t)(bb2a * HH + hh2) * TT + t2a) * DD + ddb] =
                    make_float2(v.x, v.y);
                *(float2*)&base[((size_t)(bb2b * HH + hh2) * TT + t2b) * DD + ddb] =
                    make_float2(v.z, v.w);
            }
        }
    }
}

// ---------------------------------------------------------------------------
// Tensor-core flash attention (unchanged from round 3; 1257us config).
// ---------------------------------------------------------------------------
__global__ __launch_bounds__(128)
void flash_mma()
{
    extern __shared__ float sm[];
    float* Qs = sm;                  // [128][68]
    float* Ks = sm + 128 * 68;       // [64][68]
    float* Vt = sm + 192 * 68;       // [64][68]

    const int bz = blockIdx.z, hh = blockIdx.y;
    const int qbase = blockIdx.x * 128;
    const int tid  = threadIdx.x;
    const int lane = tid & 31;
    const int w    = tid >> 5;
    const unsigned sbase = (unsigned)__cvta_generic_to_shared(sm);

    const float* __restrict__ Qg = g_q + ((size_t)(bz * HH + hh) * TT + qbase) * DD;
    const float* __restrict__ Kg = g_k + (size_t)(bz * HH + hh) * TT * DD;
    const float* __restrict__ Vg = g_v + (size_t)(bz * HH + hh) * TT * DD;

    const float qscale = 0.125f * 1.4426950408889634f;
    #pragma unroll
    for (int rep = 0; rep < 16; rep++) {
        const int row = (tid >> 4) + rep * 8;
        const int col = (tid & 15) * 4;
        float4 v = *(const float4*)&Qg[row * DD + col];
        float4 o;
        o.x = tf32r(v.x * qscale); o.y = tf32r(v.y * qscale);
        o.z = tf32r(v.z * qscale); o.w = tf32r(v.w * qscale);
        *(float4*)&Qs[row * 68 + col] = o;
    }

    float4 of[2][8];
    #pragma unroll
    for (int mt = 0; mt < 2; mt++)
        #pragma unroll
        for (int nf = 0; nf < 8; nf++) of[mt][nf] = make_float4(0.f, 0.f, 0.f, 0.f);
    float mrow[2][2], lrow[2][2];
    #pragma unroll
    for (int mt = 0; mt < 2; mt++) {
        mrow[mt][0] = mrow[mt][1] = -1e30f;
        lrow[mt][0] = lrow[mt][1] = 0.f;
    }

    const int grp = lane >> 3, lr = lane & 7;
    const int a_r = lr + ((grp & 1) << 3);
    const int a_k = (grp >> 1) << 2;
    const int b_n = lr + ((grp >> 1) << 3);
    const int b_k = (grp & 1) << 2;
    const int qsel = lane & 3;
    const int qb   = lane & ~3;

    for (int kt = 0; kt < 32; kt++) {
        __syncthreads();
        #pragma unroll
        for (int rep = 0; rep < 8; rep++) {
            const int row = (tid >> 4) + rep * 8;
            const int col = (tid & 15) * 4;
            float4 v = *(const float4*)&Kg[(size_t)(kt * 64 + row) * DD + col];
            float4 o;
            o.x = tf32r(v.x); o.y = tf32r(v.y); o.z = tf32r(v.z); o.w = tf32r(v.w);
            *(float4*)&Ks[row * 68 + col] = o;
        }
        {
            const int d  = tid & 63;
            const int qp = tid >> 6;
            #pragma unroll
            for (int rep = 0; rep < 8; rep++) {
                const int k4 = (qp + rep * 2) * 4;
                float4 o;
                o.x = tf32r(Vg[(size_t)(kt * 64 + k4 + 0) * DD + d]);
                o.y = tf32r(Vg[(size_t)(kt * 64 + k4 + 1) * DD + d]);
                o.z = tf32r(Vg[(size_t)(kt * 64 + k4 + 2) * DD + d]);
                o.w = tf32r(Vg[(size_t)(kt * 64 + k4 + 3) * DD + d]);
                *(float4*)&Vt[d * 68 + k4] = o;
            }
        }
        __syncthreads();

        float4 sf[2][8];
        #pragma unroll
        for (int mt = 0; mt < 2; mt++)
            #pragma unroll
            for (int nf = 0; nf < 8; nf++) sf[mt][nf] = make_float4(0.f, 0.f, 0.f, 0.f);

        #pragma unroll
        for (int ks = 0; ks < 8; ks++) {
            unsigned qa[2][4];
            #pragma unroll
            for (int mt = 0; mt < 2; mt++)
                ldsm4(qa[mt][0], qa[mt][1], qa[mt][2], qa[mt][3],
                      sbase + (unsigned)(((w * 32 + mt * 16 + a_r) * 68 + ks * 8 + a_k) << 2));
            unsigned kb[8][2];
            #pragma unroll
            for (int nfp = 0; nfp < 4; nfp++) {
                unsigned r0, r1, r2, r3;
                ldsm4(r0, r1, r2, r3,
                      sbase + (unsigned)((128 * 68 + (nfp * 16 + b_n) * 68 + ks * 8 + b_k) << 2));
                kb[2 * nfp][0] = r0; kb[2 * nfp][1] = r1;
                kb[2 * nfp + 1][0] = r2; kb[2 * nfp + 1][1] = r3;
            }
            #pragma unroll
            for (int mt = 0; mt < 2; mt++)
                #pragma unroll
                for (int nf = 0; nf < 8; nf++)
                    mma_tf32(sf[mt][nf], qa[mt][0], qa[mt][1], qa[mt][2], qa[mt][3],
                             kb[nf][0], kb[nf][1], sf[mt][nf]);
        }

        #pragma unroll
        for (int mt = 0; mt < 2; mt++) {
            float mx0 = -1e30f, mx1 = -1e30f;
            #pragma unroll
            for (int nf = 0; nf < 8; nf++) {
                mx0 = fmaxf(mx0, fmaxf(sf[mt][nf].x, sf[mt][nf].y));
                mx1 = fmaxf(mx1, fmaxf(sf[mt][nf].z, sf[mt][nf].w));
            }
            mx0 = fmaxf(mx0, __shfl_xor_sync(0xffffffffu, mx0, 1));
            mx0 = fmaxf(mx0, __shfl_xor_sync(0xffffffffu, mx0, 2));
            mx1 = fmaxf(mx1, __shfl_xor_sync(0xffffffffu, mx1, 1));
            mx1 = fmaxf(mx1, __shfl_xor_sync(0xffffffffu, mx1, 2));
            const float mn0 = fmaxf(mrow[mt][0], mx0);
            const float mn1 = fmaxf(mrow[mt][1], mx1);
            const float corr0 = fexp2(mrow[mt][0] - mn0);
            const float corr1 = fexp2(mrow[mt][1] - mn1);
            mrow[mt][0] = mn0; mrow[mt][1] = mn1;

            float rs0 = 0.f, rs1 = 0.f;
            #pragma unroll
            for (int nf = 0; nf < 8; nf++) {
                float4& s = sf[mt][nf];
                s.x = tf32r(fexp2(s.x - mn0));
                s.y = tf32r(fexp2(s.y - mn0));
                s.z = tf32r(fexp2(s.z - mn1));
                s.w = tf32r(fexp2(s.w - mn1));
                rs0 += s.x + s.y;
                rs1 += s.z + s.w;
            }
            rs0 += __shfl_xor_sync(0xffffffffu, rs0, 1);
            rs0 += __shfl_xor_sync(0xffffffffu, rs0, 2);
            rs1 += __shfl_xor_sync(0xffffffffu, rs1, 1);
            rs1 += __shfl_xor_sync(0xffffffffu, rs1, 2);
            lrow[mt][0] = lrow[mt][0] * corr0 + rs0;
            lrow[mt][1] = lrow[mt][1] * corr1 + rs1;
            #pragma unroll
            for (int nf = 0; nf < 8; nf++) {
                of[mt][nf].x *= corr0; of[mt][nf].y *= corr0;
                of[mt][nf].z *= corr1; of[mt][nf].w *= corr1;
            }
        }

        #pragma unroll
        for (int ks = 0; ks < 8; ks++) {
            unsigned vb[8][2];
            #pragma unroll
            for (int nfp = 0; nfp < 4; nfp++) {
                unsigned r0, r1, r2, r3;
                ldsm4(r0, r1, r2, r3,
                      sbase + (unsigned)((192 * 68 + (nfp * 16 + b_n) * 68 + ks * 8 + b_k) << 2));
                vb[2 * nfp][0] = r0; vb[2 * nfp][1] = r1;
                vb[2 * nfp + 1][0] = r2; vb[2 * nfp + 1][1] = r3;
            }
            #pragma unroll
            for (int mt = 0; mt < 2; mt++) {
                const float4 s = sf[mt][ks];
                const int s0 = qb + (qsel >> 1);
                const int s1 = s0 + 2;
                const float x0 = __shfl_sync(0xffffffffu, s.x, s0);
                const float y0 = __shfl_sync(0xffffffffu, s.y, s0);
                const float z0 = __shfl_sync(0xffffffffu, s.z, s0);
                const float w0 = __shfl_sync(0xffffffffu, s.w, s0);
                const float x1 = __shfl_sync(0xffffffffu, s.x, s1);
                const float y1 = __shfl_sync(0xffffffffu, s.y, s1);
                const float z1 = __shfl_sync(0xffffffffu, s.z, s1);
                const float w1 = __shfl_sync(0xffffffffu, s.w, s1);
                const bool odd = qsel & 1;
                const unsigned a0 = __float_as_uint(odd ? y0 : x0);
                const unsigned a1 = __float_as_uint(odd ? w0 : z0);
                const unsigned a2 = __float_as_uint(odd ? y1 : x1);
                const unsigned a3 = __float_as_uint(odd ? w1 : z1);
                #pragma unroll
                for (int nf = 0; nf < 8; nf++)
                    mma_tf32(of[mt][nf], a0, a1, a2, a3, vb[nf][0], vb[nf][1], of[mt][nf]);
            }
        }
    }

    #pragma unroll
    for (int mt = 0; mt < 2; mt++) {
        const float inv0 = 1.f / lrow[mt][0];
        const float inv1 = 1.f / lrow[mt][1];
        const int r0 = qbase + w * 32 + mt * 16 + (lane >> 2);
        #pragma unroll
        for (int nf = 0; nf < 8; nf++) {
            const int c = hh * 64 + nf * 8 + (lane & 3) * 2;
            *(float2*)&g_ctx[((size_t)bz * TT + r0) * CC + c] =
                make_float2(of[mt][nf].x * inv0, of[mt][nf].y * inv0);
            *(float2*)&g_ctx[((size_t)bz * TT + r0 + 8) * CC + c] =
                make_float2(of[mt][nf].z * inv1, of[mt][nf].w * inv1);
        }
    }
}

// ---------------------------------------------------------------------------

extern "C" void kernel_launch(void* const* d_in, const int* in_sizes, int n_in,
                              void* d_out, int out_size)
{
    const float* x    = (const float*)d_in[0];   // [4,2048,1024]
    const float* Wqkv = (const float*)d_in[1];   // [1024,3072]
    const float* Wo   = (const float*)d_in[2];   // [1024,1024]
    float* out = (float*)d_out;                  // [4,2048,1024]

    const int FLASH_SMEM = 256 * 68 * (int)sizeof(float);  // 69632 B
    cudaFuncSetAttribute(flash_mma, cudaFuncAttributeMaxDynamicSharedMemorySize,
                         FLASH_SMEM);
    cudaFuncSetAttribute(gemm_mma<0>, cudaFuncAttributeMaxDynamicSharedMemorySize,
                         GEMM_SMEM);
    cudaFuncSetAttribute(gemm_mma<1>, cudaFuncAttributeMaxDynamicSharedMemorySize,
                         GEMM_SMEM);

    float* wqkvt; cudaGetSymbolAddress((void**)&wqkvt, g_wqkvt);
    float* wot;   cudaGetSymbolAddress((void**)&wot,   g_wot);

    // 0) transpose + tf32-round weights into K-major scratch
    transpose_round<<<dim3(3 * CC / 32, CC / 32), dim3(32, 8)>>>(Wqkv, wqkvt, CC, 3 * CC);
    transpose_round<<<dim3(CC / 32, CC / 32), dim3(32, 8)>>>(Wo, wot, CC, CC);

    // 1) QKV = x @ W_qkv (mma.sync, L1-optimized), scattered into per-head Q/K/V
    gemm_mma<0><<<dim3(3 * CC / 128, BB * TT / 128), 128, GEMM_SMEM>>>(
        x, wqkvt, nullptr, CC, 3 * CC);

    // 2) tensor-core flash attention -> g_ctx [B,T,C]
    flash_mma<<<dim3(TT / 128, HH, BB), 128, FLASH_SMEM>>>();

    // 3) out = ctx @ W_o
    gemm_mma<1><<<dim3(CC / 128, BB * TT / 128), 128, GEMM_SMEM>>>(
        nullptr, wot, out, CC, CC);
}

// round 6
// speedup vs baseline: 7.6933x; 2.0864x over previous
#include <cuda_runtime.h>
#include <cuda_fp16.h>
#include <cstdint>

#define BB 4
#define TT 2048
#define CC 1024
#define HH 16
#define DD 64

// Scratch (static device globals: allocation-free per harness rules)
__device__ __half g_qh[BB*HH*TT*DD];   // [B,H,T,d], pre-scaled by 0.125*log2e
__device__ __half g_kh[BB*HH*TT*DD];   // [B,H,T,d]
__device__ __half g_vh[BB*HH*TT*DD];   // [B,H,T,d]
__device__ __half g_ctxh[BB*TT*CC];    // [B,T,C]
__device__ __half g_xh[BB*TT*CC];      // x in half
__device__ __half g_wqkvh[3*CC*CC];    // W_qkv^T [3C, C] half
__device__ __half g_woh[CC*CC];        // W_o^T   [C, C]  half

// ---------------------------------------------------------------------------
// helpers
// ---------------------------------------------------------------------------
__device__ __forceinline__ void mma_f16(float4& d,
                                        unsigned a0, unsigned a1, unsigned a2, unsigned a3,
                                        unsigned b0, unsigned b1,
                                        const float4& c) {
    asm volatile(
        "mma.sync.aligned.m16n8k16.row.col.f32.f16.f16.f32 "
        "{%0,%1,%2,%3}, {%4,%5,%6,%7}, {%8,%9}, {%10,%11,%12,%13};\n"
        : "=f"(d.x), "=f"(d.y), "=f"(d.z), "=f"(d.w)
        : "r"(a0), "r"(a1), "r"(a2), "r"(a3),
          "r"(b0), "r"(b1),
          "f"(c.x), "f"(c.y), "f"(c.z), "f"(c.w));
}

__device__ __forceinline__ void ldsm4(unsigned& r0, unsigned& r1, unsigned& r2, unsigned& r3,
                                      uint32_t saddr) {
    asm volatile("ldmatrix.sync.aligned.m8n8.x4.shared.b16 {%0,%1,%2,%3}, [%4];"
                 : "=r"(r0), "=r"(r1), "=r"(r2), "=r"(r3) : "r"(saddr));
}
__device__ __forceinline__ void ldsm4t(unsigned& r0, unsigned& r1, unsigned& r2, unsigned& r3,
                                       uint32_t saddr) {
    asm volatile("ldmatrix.sync.aligned.m8n8.x4.trans.shared.b16 {%0,%1,%2,%3}, [%4];"
                 : "=r"(r0), "=r"(r1), "=r"(r2), "=r"(r3) : "r"(saddr));
}

__device__ __forceinline__ unsigned h2pack(float a, float b) {
    __half2 h = __floats2half2_rn(a, b);
    return *(unsigned*)&h;
}

#define CP_ASYNC16(saddr, gptr) \
    asm volatile("cp.async.cg.shared.global [%0], [%1], 16;" \
                 :: "r"((uint32_t)(saddr)), "l"(gptr))
#define CP_COMMIT() asm volatile("cp.async.commit_group;" ::: "memory")
#define CP_WAIT0()  asm volatile("cp.async.wait_group 0;" ::: "memory")
#define CP_WAIT1()  asm volatile("cp.async.wait_group 1;" ::: "memory")
#define CP_WAIT2()  asm volatile("cp.async.wait_group 2;" ::: "memory")

// Branch-free exp2 using only FMA/ALU pipes (no MUFU).
__device__ __forceinline__ float fexp2(float y) {
    y = fmaxf(y, -126.0f);
    float t = y + 12582912.0f;
    int   n = __float_as_int(t) << 23;
    float f = y - (t - 12582912.0f);
    float p =            1.3333558e-3f;
    p = fmaf(p, f, 9.6181291e-3f);
    p = fmaf(p, f, 5.5504109e-2f);
    p = fmaf(p, f, 2.4022651e-1f);
    p = fmaf(p, f, 6.9314718e-1f);
    p = fmaf(p, f, 1.0f);
    return __int_as_float(__float_as_int(p) + n);
}

// ---------------------------------------------------------------------------
// x -> half
// ---------------------------------------------------------------------------
__global__ __launch_bounds__(256)
void cvt_half(const float* __restrict__ x, __half* __restrict__ xh, int n)
{
    const int i = (blockIdx.x * 256 + threadIdx.x) * 4;
    if (i < n) {
        float4 v = *(const float4*)(x + i);
        *(__half2*)(xh + i)     = __floats2half2_rn(v.x, v.y);
        *(__half2*)(xh + i + 2) = __floats2half2_rn(v.z, v.w);
    }
}

// ---------------------------------------------------------------------------
// Weight transpose to half: Wt[n][k] = half(W[k][n]).  W is [K, N] f32.
// ---------------------------------------------------------------------------
__global__ __launch_bounds__(256)
void transpose_half(const float* __restrict__ W, __half* __restrict__ Wt, int K, int N)
{
    __shared__ float t[32][33];
    const int n0 = blockIdx.x * 32, k0 = blockIdx.y * 32;
    const int tx = threadIdx.x, ty = threadIdx.y;   // 32 x 8
    #pragma unroll
    for (int i = 0; i < 32; i += 8)
        t[ty + i][tx] = W[(size_t)(k0 + ty + i) * N + n0 + tx];
    __syncthreads();
    #pragma unroll
    for (int i = 0; i < 32; i += 8)
        Wt[(size_t)(n0 + ty + i) * K + k0 + tx] = __float2half_rn(t[tx][ty + i]);
}

// ---------------------------------------------------------------------------
// fp16 mma GEMM: C[128,128] per CTA = A[M,K] @ Bt[N,K]^T, half in, f32 accum.
// 128 threads = 4 warps (2x2), warp tile 64x64, k-chunk 64, cp.async dbl-buf.
// MODE 0: QKV scatter epilogue (half out, Q pre-scaled). MODE 1: f32 store.
// ---------------------------------------------------------------------------
static constexpr int GSTR  = 72;                    // halves per smem row
static constexpr int GTILE = 128 * GSTR * 2;        // 18432 B per operand tile
static constexpr int GBUF  = 2 * GTILE;             // A+B per stage
static constexpr int GEMM_SMEM = 2 * GBUF;          // 73728 B

template<int MODE>
__global__ __launch_bounds__(128, 2)
void gemm_f16(const __half* __restrict__ A, const __half* __restrict__ Bt,
              float* __restrict__ Cout, int Ksz, int Nsz)
{
    extern __shared__ char smem[];
    const uint32_t sb = (uint32_t)__cvta_generic_to_shared(smem);
    const int tid = threadIdx.x, lane = tid & 31, wid = tid >> 5;
    const int wm = wid & 1, wn = wid >> 1;
    const int m0 = blockIdx.y * 128, n0 = blockIdx.x * 128;

    const __half* __restrict__ Ag = A  + (size_t)m0 * Ksz;
    const __half* __restrict__ Bg = Bt + (size_t)n0 * Ksz;

    auto stage = [&](int buf, int jj) {
        const uint32_t sA = sb + buf * GBUF;
        const uint32_t sB = sA + GTILE;
        const __half* ga = Ag + jj * 64;
        const __half* gb = Bg + jj * 64;
        #pragma unroll
        for (int it = 0; it < 8; it++) {
            const int idx = tid + it * 128;      // 0..1023
            const int row = idx >> 3;
            const int c8  = (idx & 7) << 3;
            CP_ASYNC16(sA + ((row * GSTR + c8) << 1), ga + (size_t)row * Ksz + c8);
            CP_ASYNC16(sB + ((row * GSTR + c8) << 1), gb + (size_t)row * Ksz + c8);
        }
    };

    const int NCH = Ksz / 64;
    stage(0, 0); CP_COMMIT();
    stage(1, 1); CP_COMMIT();

    float4 Cf[4][8];
    #pragma unroll
    for (int i = 0; i < 4; i++)
        #pragma unroll
        for (int j = 0; j < 8; j++) Cf[i][j] = make_float4(0.f, 0.f, 0.f, 0.f);

    const int grp = lane >> 3, lr = lane & 7;
    const int a_r  = lr + ((grp & 1) << 3);
    const int a_kh = (grp >> 1) << 3;
    const int b_n  = lr + ((grp >> 1) << 3);
    const int b_kh = (grp & 1) << 3;

    for (int j = 0; j < NCH; j++) {
        if (j + 1 < NCH) { CP_WAIT1(); } else { CP_WAIT0(); }
        __syncthreads();
        const uint32_t sA = sb + (j & 1) * GBUF;
        const uint32_t sB = sA + GTILE;

        #pragma unroll
        for (int ks = 0; ks < 4; ks++) {
            unsigned af[4][4];
            #pragma unroll
            for (int mt = 0; mt < 4; mt++)
                ldsm4(af[mt][0], af[mt][1], af[mt][2], af[mt][3],
                      sA + (((wm * 64 + mt * 16 + a_r) * GSTR + ks * 16 + a_kh) << 1));
            unsigned bf[8][2];
            #pragma unroll
            for (int nfp = 0; nfp < 4; nfp++) {
                unsigned r0, r1, r2, r3;
                ldsm4(r0, r1, r2, r3,
                      sB + (((wn * 64 + nfp * 16 + b_n) * GSTR + ks * 16 + b_kh) << 1));
                bf[2 * nfp][0] = r0; bf[2 * nfp][1] = r1;
                bf[2 * nfp + 1][0] = r2; bf[2 * nfp + 1][1] = r3;
            }
            #pragma unroll
            for (int mt = 0; mt < 4; mt++)
                #pragma unroll
                for (int nf = 0; nf < 8; nf++)
                    mma_f16(Cf[mt][nf], af[mt][0], af[mt][1], af[mt][2], af[mt][3],
                            bf[nf][0], bf[nf][1], Cf[mt][nf]);
        }
        __syncthreads();
        if (j + 2 < NCH) { stage(j & 1, j + 2); CP_COMMIT(); }
    }

    const float qsc = 0.125f * 1.4426950408889634f;
    #pragma unroll
    for (int mt = 0; mt < 4; mt++) {
        const int r0 = m0 + wm * 64 + mt * 16 + (lane >> 2);
        #pragma unroll
        for (int nf = 0; nf < 8; nf++) {
            const int c0 = n0 + wn * 64 + nf * 8 + (lane & 3) * 2;
            float4 v = Cf[mt][nf];
            if (MODE == 1) {
                *(float2*)&Cout[(size_t)r0 * Nsz + c0]       = make_float2(v.x, v.y);
                *(float2*)&Cout[(size_t)(r0 + 8) * Nsz + c0] = make_float2(v.z, v.w);
            } else {
                const int sel = c0 >> 10;        // 0:Q 1:K 2:V
                const int cc  = c0 & 1023;
                const int hh2 = cc >> 6;
                const int ddb = cc & 63;
                __half* base = (sel == 0) ? g_qh : (sel == 1) ? g_kh : g_vh;
                if (sel == 0) { v.x *= qsc; v.y *= qsc; v.z *= qsc; v.w *= qsc; }
                const int bb2a = r0 >> 11, t2a = r0 & 2047;
                const int bb2b = (r0 + 8) >> 11, t2b = (r0 + 8) & 2047;
                *(__half2*)&base[((size_t)(bb2a * HH + hh2) * TT + t2a) * DD + ddb] =
                    __floats2half2_rn(v.x, v.y);
                *(__half2*)&base[((size_t)(bb2b * HH + hh2) * TT + t2b) * DD + ddb] =
                    __floats2half2_rn(v.z, v.w);
            }
        }
    }
}

// ---------------------------------------------------------------------------
// fp16 flash attention. 128 threads = 4 warps; q-tile 128 (warp m32), 32
// key-tiles of 64. K/V cp.async double-buffered; Q frags preloaded; P goes
// C-frag -> A-frag via cvt (FA2 identity); V via ldmatrix.trans.
// ---------------------------------------------------------------------------
static constexpr int FSTR      = 72;                         // halves per row
static constexpr int FQ_BYTES  = 128 * FSTR * 2;             // 18432
static constexpr int FKV_HALF  = 64 * FSTR * 2;              // 9216 (one of K or V)
static constexpr int FSTAGE    = 2 * FKV_HALF;               // 18432
static constexpr int FLASH_SMEM = FQ_BYTES + 2 * FSTAGE;     // 55296

__global__ __launch_bounds__(128)
void flash_f16()
{
    extern __shared__ char smem[];
    const uint32_t sb = (uint32_t)__cvta_generic_to_shared(smem);
    const int bz = blockIdx.z, hh = blockIdx.y;
    const int qbase = blockIdx.x * 128;
    const int tid = threadIdx.x, lane = tid & 31, w = tid >> 5;

    const __half* __restrict__ Qg = g_qh + ((size_t)(bz * HH + hh) * TT + qbase) * DD;
    const __half* __restrict__ Kg = g_kh + (size_t)(bz * HH + hh) * TT * DD;
    const __half* __restrict__ Vg = g_vh + (size_t)(bz * HH + hh) * TT * DD;

    auto stageKV = [&](int buf, int kt) {
        const uint32_t sK = sb + FQ_BYTES + buf * FSTAGE;
        const uint32_t sV = sK + FKV_HALF;
        const __half* kg = Kg + (size_t)kt * 64 * DD;
        const __half* vg = Vg + (size_t)kt * 64 * DD;
        #pragma unroll
        for (int it = 0; it < 4; it++) {
            const int idx = tid + it * 128;      // 0..511
            const int row = idx >> 3;
            const int c8  = (idx & 7) << 3;
            CP_ASYNC16(sK + ((row * FSTR + c8) << 1), kg + row * 64 + c8);
            CP_ASYNC16(sV + ((row * FSTR + c8) << 1), vg + row * 64 + c8);
        }
    };

    // stage Q (group 0), then first two K/V tiles
    #pragma unroll
    for (int it = 0; it < 8; it++) {
        const int idx = tid + it * 128;
        const int row = idx >> 3;
        const int c8  = (idx & 7) << 3;
        CP_ASYNC16(sb + ((row * FSTR + c8) << 1), Qg + row * 64 + c8);
    }
    CP_COMMIT();
    stageKV(0, 0); CP_COMMIT();
    stageKV(1, 1); CP_COMMIT();

    const int grp = lane >> 3, lr = lane & 7;
    const int a_r  = lr + ((grp & 1) << 3);
    const int a_kh = (grp >> 1) << 3;
    const int b_n  = lr + ((grp >> 1) << 3);
    const int b_kh = (grp & 1) << 3;

    // Q fragments preloaded once (A-frag m16k16: 2 mt x 4 ksteps x 4 regs)
    CP_WAIT2();
    __syncthreads();
    unsigned qa[2][4][4];
    #pragma unroll
    for (int mt = 0; mt < 2; mt++)
        #pragma unroll
        for (int ks = 0; ks < 4; ks++)
            ldsm4(qa[mt][ks][0], qa[mt][ks][1], qa[mt][ks][2], qa[mt][ks][3],
                  sb + (((w * 32 + mt * 16 + a_r) * FSTR + ks * 16 + a_kh) << 1));

    float4 of[2][8];
    #pragma unroll
    for (int mt = 0; mt < 2; mt++)
        #pragma unroll
        for (int nf = 0; nf < 8; nf++) of[mt][nf] = make_float4(0.f, 0.f, 0.f, 0.f);
    float mrow[2][2], lrow[2][2];
    #pragma unroll
    for (int mt = 0; mt < 2; mt++) {
        mrow[mt][0] = mrow[mt][1] = -1e30f;
        lrow[mt][0] = lrow[mt][1] = 0.f;
    }

    for (int kt = 0; kt < 32; kt++) {
        if (kt + 1 < 32) { CP_WAIT1(); } else { CP_WAIT0(); }
        __syncthreads();
        const uint32_t sK = sb + FQ_BYTES + (kt & 1) * FSTAGE;
        const uint32_t sV = sK + FKV_HALF;

        // ---- S = Q @ K^T : m32 x n64, k=64 in 4 k16 steps ----
        float4 sf[2][8];
        #pragma unroll
        for (int mt = 0; mt < 2; mt++)
            #pragma unroll
            for (int nf = 0; nf < 8; nf++) sf[mt][nf] = make_float4(0.f, 0.f, 0.f, 0.f);

        #pragma unroll
        for (int ks = 0; ks < 4; ks++) {
            unsigned kb[8][2];
            #pragma unroll
            for (int nfp = 0; nfp < 4; nfp++) {
                unsigned r0, r1, r2, r3;
                ldsm4(r0, r1, r2, r3,
                      sK + (((nfp * 16 + b_n) * FSTR + ks * 16 + b_kh) << 1));
                kb[2 * nfp][0] = r0; kb[2 * nfp][1] = r1;
                kb[2 * nfp + 1][0] = r2; kb[2 * nfp + 1][1] = r3;
            }
            #pragma unroll
            for (int mt = 0; mt < 2; mt++)
                #pragma unroll
                for (int nf = 0; nf < 8; nf++)
                    mma_f16(sf[mt][nf], qa[mt][ks][0], qa[mt][ks][1],
                            qa[mt][ks][2], qa[mt][ks][3],
                            kb[nf][0], kb[nf][1], sf[mt][nf]);
        }

        // ---- online softmax (Q pre-scaled to log2 domain) ----
        #pragma unroll
        for (int mt = 0; mt < 2; mt++) {
            float mx0 = -1e30f, mx1 = -1e30f;
            #pragma unroll
            for (int nf = 0; nf < 8; nf++) {
                mx0 = fmaxf(mx0, fmaxf(sf[mt][nf].x, sf[mt][nf].y));
                mx1 = fmaxf(mx1, fmaxf(sf[mt][nf].z, sf[mt][nf].w));
            }
            mx0 = fmaxf(mx0, __shfl_xor_sync(0xffffffffu, mx0, 1));
            mx0 = fmaxf(mx0, __shfl_xor_sync(0xffffffffu, mx0, 2));
            mx1 = fmaxf(mx1, __shfl_xor_sync(0xffffffffu, mx1, 1));
            mx1 = fmaxf(mx1, __shfl_xor_sync(0xffffffffu, mx1, 2));
            const float mn0 = fmaxf(mrow[mt][0], mx0);
            const float mn1 = fmaxf(mrow[mt][1], mx1);
            const float corr0 = fexp2(mrow[mt][0] - mn0);
            const float corr1 = fexp2(mrow[mt][1] - mn1);
            mrow[mt][0] = mn0; mrow[mt][1] = mn1;

            float rs0 = 0.f, rs1 = 0.f;
            #pragma unroll
            for (int nf = 0; nf < 8; nf++) {
                float4& s = sf[mt][nf];
                s.x = fexp2(s.x - mn0);
                s.y = fexp2(s.y - mn0);
                s.z = fexp2(s.z - mn1);
                s.w = fexp2(s.w - mn1);
                rs0 += s.x + s.y;
                rs1 += s.z + s.w;
            }
            rs0 += __shfl_xor_sync(0xffffffffu, rs0, 1);
            rs0 += __shfl_xor_sync(0xffffffffu, rs0, 2);
            rs1 += __shfl_xor_sync(0xffffffffu, rs1, 1);
            rs1 += __shfl_xor_sync(0xffffffffu, rs1, 2);
            lrow[mt][0] = lrow[mt][0] * corr0 + rs0;
            lrow[mt][1] = lrow[mt][1] * corr1 + rs1;
            #pragma unroll
            for (int nf = 0; nf < 8; nf++) {
                of[mt][nf].x *= corr0; of[mt][nf].y *= corr0;
                of[mt][nf].z *= corr1; of[mt][nf].w *= corr1;
            }
        }

        // ---- O += P @ V : P from C-frags via cvt, V via ldmatrix.trans ----
        #pragma unroll
        for (int s = 0; s < 4; s++) {
            unsigned vb[8][2];
            #pragma unroll
            for (int dp = 0; dp < 4; dp++) {
                unsigned r0, r1, r2, r3;
                ldsm4t(r0, r1, r2, r3,
                       sV + (((s * 16 + b_n) * FSTR + dp * 16 + b_kh) << 1));
                vb[2 * dp][0] = r0; vb[2 * dp][1] = r2;
                vb[2 * dp + 1][0] = r1; vb[2 * dp + 1][1] = r3;
            }
            #pragma unroll
            for (int mt = 0; mt < 2; mt++) {
                const unsigned a0 = h2pack(sf[mt][2 * s].x,     sf[mt][2 * s].y);
                const unsigned a1 = h2pack(sf[mt][2 * s].z,     sf[mt][2 * s].w);
                const unsigned a2 = h2pack(sf[mt][2 * s + 1].x, sf[mt][2 * s + 1].y);
                const unsigned a3 = h2pack(sf[mt][2 * s + 1].z, sf[mt][2 * s + 1].w);
                #pragma unroll
                for (int nf = 0; nf < 8; nf++)
                    mma_f16(of[mt][nf], a0, a1, a2, a3, vb[nf][0], vb[nf][1], of[mt][nf]);
            }
        }
        __syncthreads();
        if (kt + 2 < 32) { stageKV(kt & 1, kt + 2); CP_COMMIT(); }
    }

    // ---- epilogue: normalize, write context as half [B,T,C] ----
    #pragma unroll
    for (int mt = 0; mt < 2; mt++) {
        const float inv0 = 1.f / lrow[mt][0];
        const float inv1 = 1.f / lrow[mt][1];
        const int r0 = qbase + w * 32 + mt * 16 + (lane >> 2);
        #pragma unroll
        for (int nf = 0; nf < 8; nf++) {
            const int c = hh * 64 + nf * 8 + (lane & 3) * 2;
            *(__half2*)&g_ctxh[((size_t)bz * TT + r0) * CC + c] =
                __floats2half2_rn(of[mt][nf].x * inv0, of[mt][nf].y * inv0);
            *(__half2*)&g_ctxh[((size_t)bz * TT + r0 + 8) * CC + c] =
                __floats2half2_rn(of[mt][nf].z * inv1, of[mt][nf].w * inv1);
        }
    }
}

// ---------------------------------------------------------------------------

extern "C" void kernel_launch(void* const* d_in, const int* in_sizes, int n_in,
                              void* d_out, int out_size)
{
    const float* x    = (const float*)d_in[0];   // [4,2048,1024]
    const float* Wqkv = (const float*)d_in[1];   // [1024,3072]
    const float* Wo   = (const float*)d_in[2];   // [1024,1024]
    float* out = (float*)d_out;                  // [4,2048,1024]

    cudaFuncSetAttribute(flash_f16, cudaFuncAttributeMaxDynamicSharedMemorySize,
                         FLASH_SMEM);
    cudaFuncSetAttribute(gemm_f16<0>, cudaFuncAttributeMaxDynamicSharedMemorySize,
                         GEMM_SMEM);
    cudaFuncSetAttribute(gemm_f16<1>, cudaFuncAttributeMaxDynamicSharedMemorySize,
                         GEMM_SMEM);

    __half *xh, *wqkvh, *woh, *ctxh;
    cudaGetSymbolAddress((void**)&xh,    g_xh);
    cudaGetSymbolAddress((void**)&wqkvh, g_wqkvh);
    cudaGetSymbolAddress((void**)&woh,   g_woh);
    cudaGetSymbolAddress((void**)&ctxh,  g_ctxh);

    // 0) convert x to half; transpose weights into K-major half scratch
    cvt_half<<<(BB * TT * CC) / (256 * 4), 256>>>(x, xh, BB * TT * CC);
    transpose_half<<<dim3(3 * CC / 32, CC / 32), dim3(32, 8)>>>(Wqkv, wqkvh, CC, 3 * CC);
    transpose_half<<<dim3(CC / 32, CC / 32), dim3(32, 8)>>>(Wo, woh, CC, CC);

    // 1) QKV = x @ W_qkv (fp16 mma), scattered into per-head Q/K/V (half)
    gemm_f16<0><<<dim3(3 * CC / 128, BB * TT / 128), 128, GEMM_SMEM>>>(
        xh, wqkvh, nullptr, CC, 3 * CC);

    // 2) fp16 flash attention -> g_ctxh [B,T,C]
    flash_f16<<<dim3(TT / 128, HH, BB), 128, FLASH_SMEM>>>();

    // 3) out = ctx @ W_o (fp16 mma, f32 out)
    gemm_f16<1><<<dim3(CC / 128, BB * TT / 128), 128, GEMM_SMEM>>>(
        ctxh, woh, out, CC, CC);
}